// round 3
// baseline (speedup 1.0000x reference)
#include <cuda_runtime.h>
#include <cstdint>

// Problem-scale constants (capacities for static scratch; runtime sizes read
// from in_sizes where cheap).
#define NQ_CAP   20000
#define E_CAP    640000
#define DF       128           // feature dim (D == H == 128)
#define LDA      260           // padded smem row stride (floats) -> conflict-free frag loads
#define SMEM_BYTES (128 * LDA * 4)

// ---------------- static device scratch (no allocations allowed) ------------
__device__ int      g_counts [NQ_CAP];
__device__ int      g_offsets[NQ_CAP + 1];
__device__ int      g_cursor [NQ_CAP];
__device__ int      g_eids   [E_CAP];
__device__ float    g_agg    [(size_t)NQ_CAP * DF];
__device__ uint32_t g_w1e[256 * 128];   // We1 as tf32 bit patterns
__device__ uint32_t g_w2e[128 * 128];   // We2
__device__ uint32_t g_w1n[256 * 128];   // Wn1
__device__ uint32_t g_w2n[128 * 128];   // Wn2

// ---------------- helpers ---------------------------------------------------
__device__ __forceinline__ uint32_t f2tf(float x) {
    uint32_t u;
    asm("cvt.rna.tf32.f32 %0, %1;" : "=r"(u) : "f"(x));
    return u;
}
__device__ __forceinline__ float silu(float x) {
    return x / (1.0f + __expf(-x));
}
__device__ __forceinline__ void mma8(float c[4], const uint32_t a[4],
                                     uint32_t b0, uint32_t b1) {
    asm("mma.sync.aligned.m16n8k8.row.col.f32.tf32.tf32.f32 "
        "{%0,%1,%2,%3}, {%4,%5,%6,%7}, {%8,%9}, {%0,%1,%2,%3};"
        : "+f"(c[0]), "+f"(c[1]), "+f"(c[2]), "+f"(c[3])
        : "r"(a[0]), "r"(a[1]), "r"(a[2]), "r"(a[3]), "r"(b0), "r"(b1));
}

// ---------------- prep: convert weights fp32 -> tf32 bits -------------------
__global__ void prep_weights(const float* __restrict__ we1,
                             const float* __restrict__ we2,
                             const float* __restrict__ wn1,
                             const float* __restrict__ wn2) {
    int i = blockIdx.x * blockDim.x + threadIdx.x;
    if (i < 32768)       g_w1e[i]          = f2tf(we1[i]);
    else if (i < 49152)  g_w2e[i - 32768]  = f2tf(we2[i - 32768]);
    else if (i < 81920)  g_w1n[i - 49152]  = f2tf(wn1[i - 49152]);
    else if (i < 98304)  g_w2n[i - 81920]  = f2tf(wn2[i - 81920]);
}

// ---------------- CSR build -------------------------------------------------
__global__ void zero_counts(int nq) {
    int i = blockIdx.x * blockDim.x + threadIdx.x;
    if (i < nq) g_counts[i] = 0;
}
__global__ void hist_kernel(const int* __restrict__ ei, int E) {
    int e = blockIdx.x * blockDim.x + threadIdx.x;
    if (e < E) atomicAdd(&g_counts[ei[e]], 1);
}
__global__ void scan_kernel(int nq) {
    __shared__ int part[1024];
    int tid = threadIdx.x;
    const int CH = 20;                     // 1024*20 >= 20000
    int loc[CH];
    int base = tid * CH;
    int s = 0;
#pragma unroll
    for (int i = 0; i < CH; i++) {
        int idx = base + i;
        loc[i] = (idx < nq) ? g_counts[idx] : 0;
        s += loc[i];
    }
    part[tid] = s;
    __syncthreads();
    for (int off = 1; off < 1024; off <<= 1) {
        int v = (tid >= off) ? part[tid - off] : 0;
        __syncthreads();
        part[tid] += v;
        __syncthreads();
    }
    int ex = part[tid] - s;                // exclusive prefix for this chunk
#pragma unroll
    for (int i = 0; i < CH; i++) {
        int idx = base + i;
        if (idx < nq) { g_offsets[idx] = ex; g_cursor[idx] = ex; }
        ex += loc[i];
    }
    if (tid == 1023) g_offsets[nq] = part[1023];
}
__global__ void scatter_kernel(const int* __restrict__ ei, int E) {
    int e = blockIdx.x * blockDim.x + threadIdx.x;
    if (e < E) {
        int r = ei[e];
        int pos = atomicAdd(&g_cursor[r], 1);
        g_eids[pos] = e;
    }
}

// ---------------- core MMA loop ---------------------------------------------
// Warp tiling: block = 256 thr = 8 warps arranged 4(M) x 2(N).
// Warp tile 32x64, built from m16n8k8 tf32 mma (2 m-tiles x 8 n-tiles).
__device__ __forceinline__ void mma_tiles(const uint32_t* __restrict__ As,
                                          const uint32_t* __restrict__ Bw,
                                          int ksteps, float acc[2][8][4],
                                          int warp_m, int warp_n,
                                          int gid, int tg) {
    for (int ks = 0; ks < ksteps; ks++) {
        int k0 = ks * 8;
        uint32_t a[2][4];
#pragma unroll
        for (int mt = 0; mt < 2; mt++) {
            const uint32_t* ap = As + (warp_m * 32 + mt * 16 + gid) * LDA + k0 + tg;
            a[mt][0] = ap[0];
            a[mt][1] = ap[8 * LDA];
            a[mt][2] = ap[4];
            a[mt][3] = ap[8 * LDA + 4];
        }
#pragma unroll
        for (int nt = 0; nt < 8; nt++) {
            int n = warp_n * 64 + nt * 8 + gid;
            uint32_t b0 = Bw[(k0 + tg) * 128 + n];
            uint32_t b1 = Bw[(k0 + tg + 4) * 128 + n];
#pragma unroll
            for (int mt = 0; mt < 2; mt++)
                mma8(acc[mt][nt], a[mt], b0, b1);
        }
    }
}

// ---------------- fused 2-layer MLP GEMM kernel -----------------------------
// MODE 0: edge model.  A row e = [h_q[row[e]], h_kv[col[e]]], out = silu(L2), write mij.
// MODE 1: node model.  A row n = [h_q[n], agg[n]],            out = L2 + h_q[n] (+bias2 in acc).
template <int MODE>
__global__ void __launch_bounds__(256, 1)
gemm_kernel(const float* __restrict__ Aq, const float* __restrict__ Akv,
            const int* __restrict__ ei, int Ecnt,
            const float* __restrict__ bias1, const float* __restrict__ bias2,
            float* __restrict__ outp, const float* __restrict__ resid,
            int nrows) {
    extern __shared__ uint32_t As[];     // [128][LDA] tf32 bit patterns
    int tid = threadIdx.x;

    // ---- gather A tile (128 rows x 256 cols) into smem as tf32 ----
    {
        int r = tid >> 1, half = tid & 1;
        int rowg = blockIdx.x * 128 + r;
        const float4* src;
        bool ok = true;
        if (MODE == 0) {
            int qi = ei[rowg];
            int ki = ei[Ecnt + rowg];
            src = half ? (const float4*)(Akv + (size_t)ki * DF)
                       : (const float4*)(Aq  + (size_t)qi * DF);
        } else {
            ok = rowg < nrows;
            int n = ok ? rowg : 0;
            src = half ? (const float4*)(g_agg + (size_t)n * DF)
                       : (const float4*)(Aq    + (size_t)n * DF);
        }
#pragma unroll
        for (int j = 0; j < 32; j++) {
            float4 v = ok ? src[j] : make_float4(0.f, 0.f, 0.f, 0.f);
            uint4 u;
            u.x = f2tf(v.x); u.y = f2tf(v.y); u.z = f2tf(v.z); u.w = f2tf(v.w);
            *(uint4*)&As[r * LDA + (half * 32 + j) * 4] = u;
        }
    }
    __syncthreads();

    int lane = tid & 31, wid = tid >> 5;
    int warp_m = wid >> 1, warp_n = wid & 1;
    int gid = lane >> 2, tg = lane & 3;

    const uint32_t* W1 = (MODE == 0) ? g_w1e : g_w1n;
    const uint32_t* W2 = (MODE == 0) ? g_w2e : g_w2n;

    // ---- layer 1: [128x256] @ [256x128] + bias1, SiLU ----
    float acc[2][8][4];
#pragma unroll
    for (int nt = 0; nt < 8; nt++) {
        int col = warp_n * 64 + nt * 8 + tg * 2;
        float b0 = bias1[col], b1 = bias1[col + 1];
#pragma unroll
        for (int mt = 0; mt < 2; mt++) {
            acc[mt][nt][0] = b0; acc[mt][nt][1] = b1;
            acc[mt][nt][2] = b0; acc[mt][nt][3] = b1;
        }
    }
    mma_tiles(As, W1, 256 / 8, acc, warp_m, warp_n, gid, tg);
    __syncthreads();   // everyone done reading As before hidden overwrite

    // SiLU + store hidden (tf32 bits) back into As[:, 0:128]
#pragma unroll
    for (int mt = 0; mt < 2; mt++) {
        int row = warp_m * 32 + mt * 16 + gid;
#pragma unroll
        for (int nt = 0; nt < 8; nt++) {
            int col = warp_n * 64 + nt * 8 + tg * 2;
            As[row * LDA + col]           = f2tf(silu(acc[mt][nt][0]));
            As[row * LDA + col + 1]       = f2tf(silu(acc[mt][nt][1]));
            As[(row + 8) * LDA + col]     = f2tf(silu(acc[mt][nt][2]));
            As[(row + 8) * LDA + col + 1] = f2tf(silu(acc[mt][nt][3]));
        }
    }
    __syncthreads();

    // ---- layer 2: [128x128] @ [128x128] + bias2 ----
#pragma unroll
    for (int nt = 0; nt < 8; nt++) {
        int col = warp_n * 64 + nt * 8 + tg * 2;
        float b0 = bias2[col], b1 = bias2[col + 1];
#pragma unroll
        for (int mt = 0; mt < 2; mt++) {
            acc[mt][nt][0] = b0; acc[mt][nt][1] = b1;
            acc[mt][nt][2] = b0; acc[mt][nt][3] = b1;
        }
    }
    mma_tiles(As, W2, 128 / 8, acc, warp_m, warp_n, gid, tg);

    // ---- epilogue ----
#pragma unroll
    for (int mt = 0; mt < 2; mt++) {
        int row = warp_m * 32 + mt * 16 + gid;
        int rg0 = blockIdx.x * 128 + row;
        int rg1 = rg0 + 8;
#pragma unroll
        for (int nt = 0; nt < 8; nt++) {
            int col = warp_n * 64 + nt * 8 + tg * 2;
            if (MODE == 0) {
                float* o0 = outp + (size_t)rg0 * DF + col;
                float* o1 = outp + (size_t)rg1 * DF + col;
                o0[0] = silu(acc[mt][nt][0]); o0[1] = silu(acc[mt][nt][1]);
                o1[0] = silu(acc[mt][nt][2]); o1[1] = silu(acc[mt][nt][3]);
            } else {
                if (rg0 < nrows) {
                    const float* h = resid + (size_t)rg0 * DF + col;
                    float* o = outp + (size_t)rg0 * DF + col;
                    o[0] = acc[mt][nt][0] + h[0];
                    o[1] = acc[mt][nt][1] + h[1];
                }
                if (rg1 < nrows) {
                    const float* h = resid + (size_t)rg1 * DF + col;
                    float* o = outp + (size_t)rg1 * DF + col;
                    o[0] = acc[mt][nt][2] + h[0];
                    o[1] = acc[mt][nt][3] + h[1];
                }
            }
        }
    }
}

// ---------------- CSR aggregation: agg[n] = sum over edges of mij -----------
__global__ void agg_kernel(const float* __restrict__ mij, int nq) {
    int w = (blockIdx.x * blockDim.x + threadIdx.x) >> 5;
    if (w >= nq) return;
    int lane = threadIdx.x & 31;
    float4 s = make_float4(0.f, 0.f, 0.f, 0.f);
    int beg = g_offsets[w], end = g_offsets[w + 1];
    for (int i = beg; i < end; i++) {
        int e = g_eids[i];
        float4 v = ((const float4*)(mij + (size_t)e * DF))[lane];
        s.x += v.x; s.y += v.y; s.z += v.z; s.w += v.w;
    }
    ((float4*)(g_agg + (size_t)w * DF))[lane] = s;
}

// ---------------- launch ----------------------------------------------------
extern "C" void kernel_launch(void* const* d_in, const int* in_sizes, int n_in,
                              void* d_out, int out_size) {
    const float* h_q  = (const float*)d_in[0];
    const float* h_kv = (const float*)d_in[1];
    const int*   ei   = (const int*)d_in[2];     // int32! (JAX x64 disabled)
    const float* We1  = (const float*)d_in[3];
    const float* be1  = (const float*)d_in[4];
    const float* We2  = (const float*)d_in[5];
    const float* be2  = (const float*)d_in[6];
    const float* Wn1  = (const float*)d_in[7];
    const float* bn1  = (const float*)d_in[8];
    const float* Wn2  = (const float*)d_in[9];
    const float* bn2  = (const float*)d_in[10];

    int nq = in_sizes[0] / DF;          // 20000
    int E  = in_sizes[2] / 2;           // 640000

    float* out_h = (float*)d_out;                       // h_q_new [nq,128]
    float* out_m = (float*)d_out + (size_t)nq * DF;     // mij     [E,128]

    cudaFuncSetAttribute(gemm_kernel<0>,
                         cudaFuncAttributeMaxDynamicSharedMemorySize, SMEM_BYTES);
    cudaFuncSetAttribute(gemm_kernel<1>,
                         cudaFuncAttributeMaxDynamicSharedMemorySize, SMEM_BYTES);

    prep_weights<<<(98304 + 255) / 256, 256>>>(We1, We2, Wn1, Wn2);
    zero_counts<<<(nq + 255) / 256, 256>>>(nq);
    hist_kernel<<<(E + 255) / 256, 256>>>(ei, E);
    scan_kernel<<<1, 1024>>>(nq);
    scatter_kernel<<<(E + 255) / 256, 256>>>(ei, E);

    gemm_kernel<0><<<E / 128, 256, SMEM_BYTES>>>(
        h_q, h_kv, ei, E, be1, be2, out_m, nullptr, E);

    agg_kernel<<<(nq + 7) / 8, 256>>>(out_m, nq);

    gemm_kernel<1><<<(nq + 127) / 128, 256, SMEM_BYTES>>>(
        h_q, nullptr, nullptr, 0, bn1, bn2, out_h, h_q, nq);
}